// round 2
// baseline (speedup 1.0000x reference)
#include <cuda_runtime.h>
#include <cuda_bf16.h>

#define IMG   256
#define NEARP 0.1f
#define FARP  100.0f
#define CHUNKF 256

#define MAXV 16384
#define MAXF 32768

// Per-vertex screen data: (sx, sy, z_cam, 1/max(z,1e-4))
__device__ float4 g_vs[MAXV];
// Per-face linear coefficients:
//   w0 = A.x + px*A.y + py*A.z   (already divided by +area)
//   w1 = A.w + px*B.x + py*B.y
//   inv_z = E + w0*B.z + w1*B.w
__device__ float4 g_fA[MAXF];
__device__ float4 g_fB[MAXF];
__device__ float  g_fE[MAXF];

// ---------------------------------------------------------------------------
// Kernel 1: vertex transform (look_at collapses to diag(1,1,zn); perspective)
// ---------------------------------------------------------------------------
__global__ void vert_k(const float* __restrict__ v, int n)
{
    int i = blockIdx.x * blockDim.x + threadIdx.x;
    if (i >= n) return;
    const float ez = 2.7320508075688772f;       // 1/tan(30deg) + 1
    const float wdt = 0.57735026918962576f;     // tan(30deg)
    float zn = ez / sqrtf(ez * ez);             // replicate ref's normalize rounding
    float vx = v[3 * i + 0];
    float vy = v[3 * i + 1];
    float vz = v[3 * i + 2];
    float z  = (vz + ez) * zn;
    float zs = (fabsf(z) < 1e-5f) ? 1e-5f : z;
    float sx = vx / (zs * wdt);
    float sy = vy / (zs * wdt);
    float zc = fmaxf(z, 1e-4f);
    g_vs[i] = make_float4(sx, sy, z, 1.0f / zc);
}

// ---------------------------------------------------------------------------
// Kernel 2: face setup. Reversed (fill_back) faces are mathematically
// identical in coverage and depth, so only the NF originals are processed.
// Orientation normalized so area > 0; invalid faces get poison coefficients.
// ---------------------------------------------------------------------------
__global__ void face_k(const int* __restrict__ faces, int nf, int nv, int B)
{
    int f = blockIdx.x * blockDim.x + threadIdx.x;
    if (f >= nf * B) return;
    int b = f / nf;
    int i0 = faces[3 * f + 0];
    int i1 = faces[3 * f + 1];
    int i2 = faces[3 * f + 2];
    float4 p0 = g_vs[b * nv + i0];
    float4 p1 = g_vs[b * nv + i1];
    float4 p2 = g_vs[b * nv + i2];

    bool ok = (p0.z > NEARP) && (p1.z > NEARP) && (p2.z > NEARP);
    float area = (p1.x - p0.x) * (p2.y - p0.y) - (p2.x - p0.x) * (p1.y - p0.y);
    ok = ok && (fabsf(area) > 1e-8f);

    if (!ok) {
        g_fA[f] = make_float4(-1e30f, 0.0f, 0.0f, -1e30f);
        g_fB[f] = make_float4(0.0f, 0.0f, 0.0f, 0.0f);
        g_fE[f] = 1.0f;
        return;
    }
    if (area < 0.0f) {  // swap v1<->v2: same barycentric set, positive area
        float4 t = p1; p1 = p2; p2 = t;
        area = -area;
    }
    float ia = 1.0f / area;
    float a0 = (p1.x * p2.y - p2.x * p1.y) * ia;
    float b0 = (p1.y - p2.y) * ia;
    float c0 = (p2.x - p1.x) * ia;
    float a1 = (p2.x * p0.y - p0.x * p2.y) * ia;
    float b1 = (p2.y - p0.y) * ia;
    float c1 = (p0.x - p2.x) * ia;
    float d0 = p0.w - p2.w;   // izc0 - izc2
    float d1 = p1.w - p2.w;   // izc1 - izc2
    g_fA[f] = make_float4(a0, b0, c0, a1);
    g_fB[f] = make_float4(b1, c1, d0, d1);
    g_fE[f] = p2.w;           // izc2
}

// ---------------------------------------------------------------------------
// Kernel 3: rasterize. One thread = one pixel; faces staged through shared
// memory in chunks of 256 (broadcast reads). Track max(inv_z) over valid
// faces; final depth = 1/max (== min zp), else FAR.
// valid  <=>  w0,w1,w2 >= 0  &&  0.01 < inv_z < 10   (zp in (NEAR,FAR))
// ---------------------------------------------------------------------------
__global__ void __launch_bounds__(256) rast_k(float* __restrict__ out, int nf)
{
    __shared__ float4 sA[CHUNKF];
    __shared__ float4 sB[CHUNKF];
    __shared__ float  sE[CHUNKF];

    int b    = blockIdx.y;
    int tile = blockIdx.x;            // 16x16 grid of 16x16-px tiles
    int tid  = threadIdx.x;
    int ix = ((tile & 15) << 4) | (tid & 15);
    int iy = ((tile >> 4) << 4) | (tid >> 4);
    float px = (float)(2 * ix + 1 - IMG) * (1.0f / IMG);
    float py = (float)(2 * iy + 1 - IMG) * (1.0f / IMG);

    float best = 0.0f;
    int base = b * nf;

    for (int c0 = 0; c0 < nf; c0 += CHUNKF) {
        int idx = c0 + tid;
        if (idx < nf) {
            sA[tid] = g_fA[base + idx];
            sB[tid] = g_fB[base + idx];
            sE[tid] = g_fE[base + idx];
        } else {
            sA[tid] = make_float4(-1e30f, 0.0f, 0.0f, -1e30f);
            sB[tid] = make_float4(0.0f, 0.0f, 0.0f, 0.0f);
            sE[tid] = 1.0f;
        }
        __syncthreads();

        #pragma unroll 8
        for (int j = 0; j < CHUNKF; ++j) {
            float4 A  = sA[j];
            float4 Bv = sB[j];
            float  e  = sE[j];
            float w0 = fmaf(py, A.z,  fmaf(px, A.y,  A.x));
            float w1 = fmaf(py, Bv.y, fmaf(px, Bv.x, A.w));
            float w2 = 1.0f - w0 - w1;
            float iz = fmaf(w1, Bv.w, fmaf(w0, Bv.z, e));
            float m  = fminf(fminf(w0, w1), w2);
            bool ok  = (m >= 0.0f) && (iz > 0.01f) && (iz < 10.0f);
            best = fmaxf(best, ok ? iz : 0.0f);
        }
        __syncthreads();
    }

    float depth = (best > 0.0f) ? (1.0f / best) : FARP;
    out[(b * IMG + iy) * IMG + ix] = depth;
}

// ---------------------------------------------------------------------------
extern "C" void kernel_launch(void* const* d_in, const int* in_sizes, int n_in,
                              void* d_out, int out_size)
{
    const float* verts = (const float*)d_in[0];
    const int*   faces = (const int*)d_in[1];
    float*       out   = (float*)d_out;

    int B = out_size / (IMG * IMG);
    if (B < 1) B = 1;
    int nv = in_sizes[0] / (3 * B);
    int nf = in_sizes[1] / (3 * B);
    int nvt = B * nv;
    int nft = B * nf;

    vert_k<<<(nvt + 255) / 256, 256>>>(verts, nvt);
    face_k<<<(nft + 255) / 256, 256>>>(faces, nf, nv, B);
    dim3 grid(256, B);
    rast_k<<<grid, 256>>>(out, nf);
}

// round 3
// speedup vs baseline: 4.3382x; 4.3382x over previous
#include <cuda_runtime.h>
#include <cuda_bf16.h>

#define IMG    256
#define NEARP  0.1f
#define FARP   100.0f
#define CHUNKF 256
#define NTILE  256        // 16x16 tiles of 16x16 px
#define CAP    8192       // faces per tile capacity (>= NF max)
#define MAXB   2
#define SLICES 4

#define MAXV 16384
#define MAXF 32768

// Per-vertex screen data: (sx, sy, z_cam, 1/max(z,1e-4))
__device__ float4 g_vs[MAXV];
// Per-face linear coefficients (see rast_k)
__device__ float4 g_fA[MAXF];
__device__ float4 g_fB[MAXF];
__device__ float  g_fE[MAXF];
// Tile binning
__device__ int      g_cnt[MAXB * NTILE];
__device__ int      g_list[MAXB * NTILE * CAP];
// Per-pixel running max(inv_z) as uint bit pattern (valid: nonneg floats)
__device__ unsigned g_best[MAXB * IMG * IMG];

// ---------------------------------------------------------------------------
__global__ void clear_k(int npx, int ncnt)
{
    int i = blockIdx.x * blockDim.x + threadIdx.x;
    if (i < npx)  g_best[i] = 0u;
    if (i < ncnt) g_cnt[i]  = 0;
}

// ---------------------------------------------------------------------------
// Vertex transform: look_at collapses to diag(1,1,zn); then perspective.
// ---------------------------------------------------------------------------
__global__ void vert_k(const float* __restrict__ v, int n)
{
    int i = blockIdx.x * blockDim.x + threadIdx.x;
    if (i >= n) return;
    const float ez  = 2.7320508075688772f;   // 1/tan(30deg) + 1
    const float wdt = 0.57735026918962576f;  // tan(30deg)
    float zn = ez / sqrtf(ez * ez);          // replicate ref's normalize rounding
    float vx = v[3 * i + 0];
    float vy = v[3 * i + 1];
    float vz = v[3 * i + 2];
    float z  = (vz + ez) * zn;
    float zs = (fabsf(z) < 1e-5f) ? 1e-5f : z;
    float sx = vx / (zs * wdt);
    float sy = vy / (zs * wdt);
    float zc = fmaxf(z, 1e-4f);
    g_vs[i] = make_float4(sx, sy, z, 1.0f / zc);
}

// ---------------------------------------------------------------------------
// Face setup + tile binning. fill_back duplicates are coverage/depth-identical
// (signed-area barycentrics are orientation-invariant) so only NF originals.
// Invalid faces are simply not binned.
// ---------------------------------------------------------------------------
__global__ void face_k(const int* __restrict__ faces, int nf, int nv, int B)
{
    int f = blockIdx.x * blockDim.x + threadIdx.x;
    if (f >= nf * B) return;
    int b = f / nf;
    int i0 = faces[3 * f + 0];
    int i1 = faces[3 * f + 1];
    int i2 = faces[3 * f + 2];
    float4 p0 = g_vs[b * nv + i0];
    float4 p1 = g_vs[b * nv + i1];
    float4 p2 = g_vs[b * nv + i2];

    bool ok = (p0.z > NEARP) && (p1.z > NEARP) && (p2.z > NEARP);
    float area = (p1.x - p0.x) * (p2.y - p0.y) - (p2.x - p0.x) * (p1.y - p0.y);
    ok = ok && (fabsf(area) > 1e-8f);
    if (!ok) return;

    // Conservative pixel bbox (±1 px margin). px(ix) = (2ix+1-256)/256.
    float xmin = fminf(p0.x, fminf(p1.x, p2.x));
    float xmax = fmaxf(p0.x, fmaxf(p1.x, p2.x));
    float ymin = fminf(p0.y, fminf(p1.y, p2.y));
    float ymax = fmaxf(p0.y, fmaxf(p1.y, p2.y));
    int ixlo = (int)floorf(xmin * 128.0f + 127.5f) - 1;
    int ixhi = (int)floorf(xmax * 128.0f + 127.5f) + 1;
    int iylo = (int)floorf(ymin * 128.0f + 127.5f) - 1;
    int iyhi = (int)floorf(ymax * 128.0f + 127.5f) + 1;
    if (ixhi < 0 || ixlo > IMG - 1 || iyhi < 0 || iylo > IMG - 1) return;
    ixlo = max(ixlo, 0); ixhi = min(ixhi, IMG - 1);
    iylo = max(iylo, 0); iyhi = min(iyhi, IMG - 1);

    if (area < 0.0f) {  // swap v1<->v2: same barycentric set, positive area
        float4 t = p1; p1 = p2; p2 = t;
        area = -area;
    }
    float ia = 1.0f / area;
    float a0 = (p1.x * p2.y - p2.x * p1.y) * ia;
    float b0 = (p1.y - p2.y) * ia;
    float c0 = (p2.x - p1.x) * ia;
    float a1 = (p2.x * p0.y - p0.x * p2.y) * ia;
    float b1 = (p2.y - p0.y) * ia;
    float c1 = (p0.x - p2.x) * ia;
    float d0 = p0.w - p2.w;
    float d1 = p1.w - p2.w;
    g_fA[f] = make_float4(a0, b0, c0, a1);
    g_fB[f] = make_float4(b1, c1, d0, d1);
    g_fE[f] = p2.w;

    int tx0 = ixlo >> 4, tx1 = ixhi >> 4;
    int ty0 = iylo >> 4, ty1 = iyhi >> 4;
    for (int ty = ty0; ty <= ty1; ++ty)
        for (int tx = tx0; tx <= tx1; ++tx) {
            int t = b * NTILE + ty * 16 + tx;
            int pos = atomicAdd(&g_cnt[t], 1);
            if (pos < CAP) g_list[t * CAP + pos] = f;
        }
}

// ---------------------------------------------------------------------------
// Rasterize: one block = (tile, slice). Threads = pixels of the 16x16 tile.
// Each slice processes strided 256-face chunks of the tile's list; partial
// results merge via atomicMax on inv_z bits (order-invariant => deterministic).
//   w0 = A.x + px*A.y + py*A.z ; w1 = A.w + px*B.x + py*B.y
//   inv_z = E + w0*B.z + w1*B.w ; valid <=> min(w)>=0 && 0.01<inv_z<10
// ---------------------------------------------------------------------------
__global__ void __launch_bounds__(256) rast_k(void)
{
    __shared__ float4 sA[CHUNKF];
    __shared__ float4 sB[CHUNKF];
    __shared__ float  sE[CHUNKF];

    int tile  = blockIdx.x;
    int slice = blockIdx.y;
    int b     = blockIdx.z;
    int tid   = threadIdx.x;
    int ix = ((tile & 15) << 4) | (tid & 15);
    int iy = ((tile >> 4) << 4) | (tid >> 4);
    float px = (float)(2 * ix + 1 - IMG) * (1.0f / IMG);
    float py = (float)(2 * iy + 1 - IMG) * (1.0f / IMG);

    int n = g_cnt[b * NTILE + tile];
    if (n > CAP) n = CAP;
    const int* list = &g_list[(b * NTILE + tile) * CAP];

    float best = 0.0f;
    int stride = gridDim.y * CHUNKF;
    for (int c0 = slice * CHUNKF; c0 < n; c0 += stride) {
        int m = min(CHUNKF, n - c0);
        if (tid < m) {
            int f = list[c0 + tid];
            sA[tid] = g_fA[f];
            sB[tid] = g_fB[f];
            sE[tid] = g_fE[f];
        }
        __syncthreads();

        #pragma unroll 4
        for (int j = 0; j < m; ++j) {
            float4 A  = sA[j];
            float4 Bv = sB[j];
            float  e  = sE[j];
            float w0 = fmaf(py, A.z,  fmaf(px, A.y,  A.x));
            float w1 = fmaf(py, Bv.y, fmaf(px, Bv.x, A.w));
            float w2 = 1.0f - w0 - w1;
            float iz = fmaf(w1, Bv.w, fmaf(w0, Bv.z, e));
            float mn = fminf(fminf(w0, w1), w2);
            bool ok  = (mn >= 0.0f) && (iz > 0.01f) && (iz < 10.0f);
            best = fmaxf(best, ok ? iz : 0.0f);
        }
        __syncthreads();
    }

    if (best > 0.0f)
        atomicMax(&g_best[b * (IMG * IMG) + iy * IMG + ix], __float_as_uint(best));
}

// ---------------------------------------------------------------------------
__global__ void final_k(float* __restrict__ out, int npx)
{
    int i = blockIdx.x * blockDim.x + threadIdx.x;
    if (i >= npx) return;
    unsigned u = g_best[i];
    out[i] = (u > 0u) ? (1.0f / __uint_as_float(u)) : FARP;
}

// ---------------------------------------------------------------------------
extern "C" void kernel_launch(void* const* d_in, const int* in_sizes, int n_in,
                              void* d_out, int out_size)
{
    const float* verts = (const float*)d_in[0];
    const int*   faces = (const int*)d_in[1];
    float*       out   = (float*)d_out;

    int B = out_size / (IMG * IMG);
    if (B < 1) B = 1;
    int nv = in_sizes[0] / (3 * B);
    int nf = in_sizes[1] / (3 * B);
    int nvt = B * nv;
    int nft = B * nf;
    int npx = B * IMG * IMG;

    clear_k<<<(npx + 255) / 256, 256>>>(npx, B * NTILE);
    vert_k<<<(nvt + 255) / 256, 256>>>(verts, nvt);
    face_k<<<(nft + 255) / 256, 256>>>(faces, nf, nv, B);
    dim3 grid(NTILE, SLICES, B);
    rast_k<<<grid, 256>>>();
    final_k<<<(npx + 255) / 256, 256>>>(out, npx);
}

// round 4
// speedup vs baseline: 6.4884x; 1.4956x over previous
#include <cuda_runtime.h>
#include <cuda_bf16.h>

#define IMG    256
#define NEARP  0.1f
#define FARP   100.0f
#define CHUNKF 128
#define NTILE  256        // 16x16 tiles of 16x16 px
#define CAP    8192
#define MAXB   2
#define SLICES 32

#define MAXV 16384
#define MAXF 32768

// Per-vertex screen data: (sx, sy, z_cam, 1/max(z,1e-4))
__device__ float4 g_vs[MAXV];
// Per-face linear coefficients:
//   w0 = A.x + px*A.y + py*A.z ; w1 = A.w + px*B.x + py*B.y
//   inv_z = E + w0*B.z + w1*B.w
__device__ float4 g_fA[MAXF];
__device__ float4 g_fB[MAXF];
__device__ float  g_fE[MAXF];
// Tile binning
__device__ int      g_cnt[MAXB * NTILE];
__device__ int      g_list[MAXB * NTILE * CAP];
// Per-pixel running max(inv_z) as uint bit pattern (valid: nonneg floats)
__device__ unsigned g_best[MAXB * IMG * IMG];

// ---------------------------------------------------------------------------
// Kernel 1: clear buffers + vertex transform (independent work, fused).
// look_at collapses to diag(1,1,zn); then perspective.
// ---------------------------------------------------------------------------
__global__ void init_k(const float* __restrict__ v, int nvt, int npx, int ncnt)
{
    int i = blockIdx.x * blockDim.x + threadIdx.x;
    if (i < npx)  g_best[i] = 0u;
    if (i < ncnt) g_cnt[i]  = 0;
    if (i >= nvt) return;
    const float ez  = 2.7320508075688772f;   // 1/tan(30deg) + 1
    const float wdt = 0.57735026918962576f;  // tan(30deg)
    float zn = ez / sqrtf(ez * ez);          // replicate ref's normalize rounding
    float vx = v[3 * i + 0];
    float vy = v[3 * i + 1];
    float vz = v[3 * i + 2];
    float z  = (vz + ez) * zn;
    float zs = (fabsf(z) < 1e-5f) ? 1e-5f : z;
    float sx = vx / (zs * wdt);
    float sy = vy / (zs * wdt);
    float zc = fmaxf(z, 1e-4f);
    g_vs[i] = make_float4(sx, sy, z, 1.0f / zc);
}

// Max of linear form a + b*x + c*y over rect [x0,x1]x[y0,y1]
__device__ __forceinline__ float lin_max(float a, float b, float c,
                                         float x0, float x1, float y0, float y1)
{
    return a + b * (b > 0.0f ? x1 : x0) + c * (c > 0.0f ? y1 : y0);
}

// ---------------------------------------------------------------------------
// Kernel 2: face setup + tile binning with exact (conservative) tri-tile cull.
// fill_back duplicates are coverage/depth-identical, so only NF originals.
// ---------------------------------------------------------------------------
__global__ void face_k(const int* __restrict__ faces, int nf, int nv, int B)
{
    int f = blockIdx.x * blockDim.x + threadIdx.x;
    if (f >= nf * B) return;
    int b = f / nf;
    int i0 = faces[3 * f + 0];
    int i1 = faces[3 * f + 1];
    int i2 = faces[3 * f + 2];
    float4 p0 = g_vs[b * nv + i0];
    float4 p1 = g_vs[b * nv + i1];
    float4 p2 = g_vs[b * nv + i2];

    bool ok = (p0.z > NEARP) && (p1.z > NEARP) && (p2.z > NEARP);
    float area = (p1.x - p0.x) * (p2.y - p0.y) - (p2.x - p0.x) * (p1.y - p0.y);
    ok = ok && (fabsf(area) > 1e-8f);
    if (!ok) return;

    // Conservative pixel bbox (+-1 px). px(ix) = (2ix+1-256)/256.
    float xmin = fminf(p0.x, fminf(p1.x, p2.x));
    float xmax = fmaxf(p0.x, fmaxf(p1.x, p2.x));
    float ymin = fminf(p0.y, fminf(p1.y, p2.y));
    float ymax = fmaxf(p0.y, fmaxf(p1.y, p2.y));
    int ixlo = (int)floorf(xmin * 128.0f + 127.5f) - 1;
    int ixhi = (int)floorf(xmax * 128.0f + 127.5f) + 1;
    int iylo = (int)floorf(ymin * 128.0f + 127.5f) - 1;
    int iyhi = (int)floorf(ymax * 128.0f + 127.5f) + 1;
    if (ixhi < 0 || ixlo > IMG - 1 || iyhi < 0 || iylo > IMG - 1) return;
    ixlo = max(ixlo, 0); ixhi = min(ixhi, IMG - 1);
    iylo = max(iylo, 0); iyhi = min(iyhi, IMG - 1);

    if (area < 0.0f) {  // swap v1<->v2: same barycentric set, positive area
        float4 t = p1; p1 = p2; p2 = t;
        area = -area;
    }
    float ia = 1.0f / area;
    float a0 = (p1.x * p2.y - p2.x * p1.y) * ia;
    float b0 = (p1.y - p2.y) * ia;
    float c0 = (p2.x - p1.x) * ia;
    float a1 = (p2.x * p0.y - p0.x * p2.y) * ia;
    float b1 = (p2.y - p0.y) * ia;
    float c1 = (p0.x - p2.x) * ia;
    float d0 = p0.w - p2.w;
    float d1 = p1.w - p2.w;
    g_fA[f] = make_float4(a0, b0, c0, a1);
    g_fB[f] = make_float4(b1, c1, d0, d1);
    g_fE[f] = p2.w;
    // w2 = 1 - w0 - w1 as a linear form
    float a2 = 1.0f - a0 - a1;
    float b2 = -b0 - b1;
    float c2 = -c0 - c1;

    float e0 = 1e-5f * (fabsf(a0) + fabsf(b0) + fabsf(c0));
    float e1 = 1e-5f * (fabsf(a1) + fabsf(b1) + fabsf(c1));
    float e2 = 1e-5f * (fabsf(a2) + fabsf(b2) + fabsf(c2));

    int tx0 = ixlo >> 4, tx1 = ixhi >> 4;
    int ty0 = iylo >> 4, ty1 = iyhi >> 4;
    for (int ty = ty0; ty <= ty1; ++ty) {
        // NDC extent of this tile's pixel centers, dilated by 1px
        float ry0 = (float)(2 * (ty << 4) + 1 - IMG) * (1.0f / IMG) - (2.0f / IMG);
        float ry1 = (float)(2 * ((ty << 4) + 15) + 1 - IMG) * (1.0f / IMG) + (2.0f / IMG);
        for (int tx = tx0; tx <= tx1; ++tx) {
            float rx0 = (float)(2 * (tx << 4) + 1 - IMG) * (1.0f / IMG) - (2.0f / IMG);
            float rx1 = (float)(2 * ((tx << 4) + 15) + 1 - IMG) * (1.0f / IMG) + (2.0f / IMG);
            // cull if any barycentric is negative over the whole rect
            if (lin_max(a0, b0, c0, rx0, rx1, ry0, ry1) < -e0) continue;
            if (lin_max(a1, b1, c1, rx0, rx1, ry0, ry1) < -e1) continue;
            if (lin_max(a2, b2, c2, rx0, rx1, ry0, ry1) < -e2) continue;
            int t = b * NTILE + ty * 16 + tx;
            int pos = atomicAdd(&g_cnt[t], 1);
            if (pos < CAP) g_list[t * CAP + pos] = f;
        }
    }
}

// ---------------------------------------------------------------------------
// Kernel 3: rasterize. Block = (tile, slice); 128 threads; each thread owns
// pixels (ix, iy) and (ix, iy+8). Slices take strided 128-face chunks;
// partial maxima merge via atomicMax on inv_z bits (order-invariant).
// ---------------------------------------------------------------------------
__global__ void __launch_bounds__(128) rast_k(void)
{
    __shared__ float4 sA[CHUNKF];
    __shared__ float4 sB[CHUNKF];
    __shared__ float  sE[CHUNKF];

    int tile  = blockIdx.x;
    int slice = blockIdx.y;
    int b     = blockIdx.z;
    int tid   = threadIdx.x;

    int n = g_cnt[b * NTILE + tile];
    if (n > CAP) n = CAP;
    if (slice * CHUNKF >= n) return;

    int ix = ((tile & 15) << 4) | (tid & 15);
    int iy = ((tile >> 4) << 4) | (tid >> 4);     // 0..7 within tile
    float px = (float)(2 * ix + 1 - IMG) * (1.0f / IMG);
    float py = (float)(2 * iy + 1 - IMG) * (1.0f / IMG);
    const float DY = 16.0f / IMG;                 // 8 rows down

    const int* list = &g_list[(b * NTILE + tile) * CAP];
    float best0 = 0.0f, best1 = 0.0f;

    for (int c0 = slice * CHUNKF; c0 < n; c0 += SLICES * CHUNKF) {
        int m = min(CHUNKF, n - c0);
        if (tid < m) {
            int f = list[c0 + tid];
            sA[tid] = g_fA[f];
            sB[tid] = g_fB[f];
            sE[tid] = g_fE[f];
        }
        __syncthreads();

        #pragma unroll 4
        for (int j = 0; j < m; ++j) {
            float4 A  = sA[j];
            float4 Bv = sB[j];
            float  e  = sE[j];
            float w0 = fmaf(py, A.z,  fmaf(px, A.y,  A.x));
            float w1 = fmaf(py, Bv.y, fmaf(px, Bv.x, A.w));
            float w2 = 1.0f - w0 - w1;
            float iz = fmaf(w1, Bv.w, fmaf(w0, Bv.z, e));
            bool ok  = (fminf(fminf(w0, w1), w2) >= 0.0f) &&
                       (iz > 0.01f) && (iz < 10.0f);
            best0 = fmaxf(best0, ok ? iz : 0.0f);

            float w0b = fmaf(DY, A.z,  w0);
            float w1b = fmaf(DY, Bv.y, w1);
            float w2b = 1.0f - w0b - w1b;
            float izb = fmaf(w1b, Bv.w, fmaf(w0b, Bv.z, e));
            bool okb  = (fminf(fminf(w0b, w1b), w2b) >= 0.0f) &&
                        (izb > 0.01f) && (izb < 10.0f);
            best1 = fmaxf(best1, okb ? izb : 0.0f);
        }
        __syncthreads();
    }

    unsigned* bb = &g_best[b * (IMG * IMG)];
    if (best0 > 0.0f) atomicMax(&bb[iy * IMG + ix],       __float_as_uint(best0));
    if (best1 > 0.0f) atomicMax(&bb[(iy + 8) * IMG + ix], __float_as_uint(best1));
}

// ---------------------------------------------------------------------------
__global__ void final_k(float* __restrict__ out, int npx)
{
    int i = blockIdx.x * blockDim.x + threadIdx.x;
    if (i >= npx) return;
    unsigned u = g_best[i];
    out[i] = (u > 0u) ? (1.0f / __uint_as_float(u)) : FARP;
}

// ---------------------------------------------------------------------------
extern "C" void kernel_launch(void* const* d_in, const int* in_sizes, int n_in,
                              void* d_out, int out_size)
{
    const float* verts = (const float*)d_in[0];
    const int*   faces = (const int*)d_in[1];
    float*       out   = (float*)d_out;

    int B = out_size / (IMG * IMG);
    if (B < 1) B = 1;
    int nv = in_sizes[0] / (3 * B);
    int nf = in_sizes[1] / (3 * B);
    int nvt = B * nv;
    int nft = B * nf;
    int npx = B * IMG * IMG;

    int initN = npx > nvt ? npx : nvt;
    init_k<<<(initN + 255) / 256, 256>>>(verts, nvt, npx, B * NTILE);
    face_k<<<(nft + 255) / 256, 256>>>(faces, nf, nv, B);
    dim3 grid(NTILE, SLICES, B);
    rast_k<<<grid, 128>>>();
    final_k<<<(npx + 255) / 256, 256>>>(out, npx);
}